// round 10
// baseline (speedup 1.0000x reference)
#include <cuda_runtime.h>
#include <cstdint>

#define N_NODES 65536
#define IN_FEAT 512
#define OUT_FEAT 256
#define N_REL 3
#define N_EDGES 500000
#define NEG_SLOPE 0.2f
#define EPS 1e-9f
#define NSEG (N_REL * N_NODES)          // 196608 segments
#define SCAN_BLOCKS (NSEG / 1024)       // 192

// ---------------- scratch (static device globals; no allocs allowed) ---------
__device__ float g_ha[(size_t)N_NODES * IN_FEAT];              // tf32-rounded h
__device__ float g_Wp[(size_t)N_REL * IN_FEAT * OUT_FEAT];     // tf32-rounded W
__device__ float g_z3[(size_t)N_REL * N_NODES * OUT_FEAT];     // z per relation
__device__ float g_el3[NSEG];
__device__ float g_er3[NSEG];
__device__ int   g_deg[NSEG];
__device__ int   g_off[NSEG + 1];
__device__ int   g_cur[NSEG];
__device__ int   g_blk[SCAN_BLOCKS];
__device__ int   g_srcs[(size_t)N_REL * N_EDGES];              // dst-sorted src ids

__device__ __forceinline__ uint32_t smem_u32(const void* p) {
    return (uint32_t)__cvta_generic_to_shared(p);
}
__device__ __forceinline__ void cp_async16(uint32_t saddr, const void* gaddr) {
    asm volatile("cp.async.cg.shared.global [%0], [%1], 16;" :: "r"(saddr), "l"(gaddr));
}
__device__ __forceinline__ uint32_t rna_tf32(uint32_t x) {
    asm("cvt.rna.tf32.f32 %0, %0;" : "+r"(x));
    return x;
}

// ---------------- init: out bias + zero accumulators/counters --------------
__global__ void init_out_kernel(const float* __restrict__ b, float* __restrict__ out) {
    int i = blockIdx.x * blockDim.x + threadIdx.x;
    if (i < NSEG) {
        g_el3[i] = 0.f;
        g_er3[i] = 0.f;
        g_deg[i] = 0;
    }
    if (i >= N_NODES * OUT_FEAT) return;
    int f = i & (OUT_FEAT - 1);
    out[i] = b[f] + b[OUT_FEAT + f] + b[2 * OUT_FEAT + f];
}

// ---------------- pre-round h to tf32 (RNA) once ---------------------------
__global__ void preround_h_kernel(const float* __restrict__ h) {
    size_t i = (size_t)blockIdx.x * blockDim.x + threadIdx.x;
    size_t n4 = (size_t)N_NODES * IN_FEAT / 4;
    if (i >= n4) return;
    uint4 v = ((const uint4*)h)[i];
    v.x = rna_tf32(v.x); v.y = rna_tf32(v.y);
    v.z = rna_tf32(v.z); v.w = rna_tf32(v.w);
    ((uint4*)g_ha)[i] = v;
}

// ---------------- pre-round ALL relations' W -------------------------------
__global__ void preround_w_kernel(const float* __restrict__ W) {
    int i = blockIdx.x * blockDim.x + threadIdx.x;
    int n4 = N_REL * IN_FEAT * OUT_FEAT / 4;
    if (i >= n4) return;
    uint4 v = ((const uint4*)W)[i];
    v.x = rna_tf32(v.x); v.y = rna_tf32(v.y);
    v.z = rna_tf32(v.z); v.w = rna_tf32(v.w);
    ((uint4*)g_Wp)[i] = v;
}

// ---------------- TF32 GEMM, all relations, fused logit epilogue -----------
#define GBM 128
#define GBN 128
#define GBK 32
#define LDA 36
#define LDB 136
#define A_STAGE (GBM * LDA)
#define B_STAGE (GBK * LDB)
#define STAGE_FLOATS (A_STAGE + B_STAGE)
#define NSTAGES 3
#define GEMM_SMEM_BYTES (NSTAGES * STAGE_FLOATS * 4)
#define KITERS (IN_FEAT / GBK)

__global__ __launch_bounds__(256, 2) void gemm_tf32_kernel(const float* __restrict__ al,
                                                           const float* __restrict__ ar) {
    extern __shared__ float smem[];
    const uint32_t sb0 = smem_u32(smem);
    const int tid  = threadIdx.x;
    const int bx   = blockIdx.x;
    const int by   = blockIdx.y;
    const int rel  = blockIdx.z;
    const int warp = tid >> 5, lane = tid & 31;
    const int wm = warp >> 2;
    const int wn = warp & 3;

    const int a_row_off = (lane & 7) + ((lane >> 3) & 1) * 8;
    const int a_col_off = ((lane >> 4) & 1) * 4;
    const int b_k_off = lane & 3;
    const int b_n_off = lane >> 2;

    const float* Ag0 = g_ha + (size_t)(by * GBM) * IN_FEAT;
    const float* Bg0 = g_Wp + (size_t)rel * IN_FEAT * OUT_FEAT + bx * GBN;
    const float* alr = al + rel * OUT_FEAT;
    const float* arr = ar + rel * OUT_FEAT;

    // hoisted per-thread load addressing (constant across kt)
    uint32_t a_sm[4], b_sm[4];
    const float *a_gp[4], *b_gp[4];
    #pragma unroll
    for (int i = 0; i < 4; i++) {
        int q = tid + i * 256;
        int r1 = q >> 3, c1 = q & 7;            // A: 128 rows x 8 chunks
        a_sm[i] = (uint32_t)(r1 * LDA + c1 * 4) * 4;
        a_gp[i] = Ag0 + (size_t)r1 * IN_FEAT + c1 * 4;
        int r2 = q >> 5, c2 = q & 31;           // B: 32 rows x 32 chunks
        b_sm[i] = (uint32_t)(A_STAGE + r2 * LDB + c2 * 4) * 4;
        b_gp[i] = Bg0 + (size_t)r2 * OUT_FEAT + c2 * 4;
    }

    float acc[4][4][4];
    #pragma unroll
    for (int i = 0; i < 4; i++)
        #pragma unroll
        for (int j = 0; j < 4; j++)
            #pragma unroll
            for (int v = 0; v < 4; v++) acc[i][j][v] = 0.f;

    auto load_stage = [&](int kt, int s) {
        uint32_t sbase = sb0 + (uint32_t)s * (STAGE_FLOATS * 4);
        int ka = kt * GBK;
        #pragma unroll
        for (int i = 0; i < 4; i++)
            cp_async16(sbase + a_sm[i], a_gp[i] + ka);
        size_t kb = (size_t)ka * OUT_FEAT;
        #pragma unroll
        for (int i = 0; i < 4; i++)
            cp_async16(sbase + b_sm[i], b_gp[i] + kb);
    };

    load_stage(0, 0);
    asm volatile("cp.async.commit_group;");
    load_stage(1, 1);
    asm volatile("cp.async.commit_group;");
    load_stage(2, 2);
    asm volatile("cp.async.commit_group;");

    int slot = 0;
    for (int kt = 0; kt < KITERS; kt++) {
        asm volatile("cp.async.wait_group 2;");
        __syncthreads();

        const float* As = smem + slot * STAGE_FLOATS;
        const float* Bs = As + A_STAGE;

        #pragma unroll
        for (int k8 = 0; k8 < GBK / 8; k8++) {
            uint32_t a[4][4];
            #pragma unroll
            for (int i = 0; i < 4; i++) {
                const float* p = As + (wm * 64 + i * 16 + a_row_off) * LDA + k8 * 8 + a_col_off;
                uint32_t addr = smem_u32(p);
                asm volatile("ldmatrix.sync.aligned.m8n8.x4.shared.b16 {%0,%1,%2,%3}, [%4];"
                             : "=r"(a[i][0]), "=r"(a[i][1]), "=r"(a[i][2]), "=r"(a[i][3])
                             : "r"(addr));
            }
            uint32_t bf[4][2];
            #pragma unroll
            for (int j = 0; j < 4; j++) {
                const float* p = Bs + (k8 * 8 + b_k_off) * LDB + wn * 32 + j * 8 + b_n_off;
                bf[j][0] = __float_as_uint(p[0]);
                bf[j][1] = __float_as_uint(p[4 * LDB]);
            }
            #pragma unroll
            for (int i = 0; i < 4; i++)
                #pragma unroll
                for (int j = 0; j < 4; j++) {
                    asm volatile(
                        "mma.sync.aligned.m16n8k8.row.col.f32.tf32.tf32.f32 "
                        "{%0,%1,%2,%3}, {%4,%5,%6,%7}, {%8,%9}, {%0,%1,%2,%3};"
                        : "+f"(acc[i][j][0]), "+f"(acc[i][j][1]),
                          "+f"(acc[i][j][2]), "+f"(acc[i][j][3])
                        : "r"(a[i][0]), "r"(a[i][1]), "r"(a[i][2]), "r"(a[i][3]),
                          "r"(bf[j][0]), "r"(bf[j][1]));
                }
        }
        __syncthreads();
        if (kt + 3 < KITERS) load_stage(kt + 3, slot);
        asm volatile("cp.async.commit_group;");
        slot = (slot == NSTAGES - 1) ? 0 : slot + 1;
    }

    float* zb = g_z3 + (size_t)rel * N_NODES * OUT_FEAT;
    float* elb = g_el3 + rel * N_NODES;
    float* erb = g_er3 + rel * N_NODES;
    const int row0 = by * GBM + wm * 64;
    const int col0 = bx * GBN + wn * 32;
    const int gr = lane >> 2;
    const int gc = (lane & 3) * 2;
    #pragma unroll
    for (int i = 0; i < 4; i++) {
        float* r0p = zb + (size_t)(row0 + i * 16 + gr) * OUT_FEAT + col0 + gc;
        float* r1p = r0p + (size_t)8 * OUT_FEAT;
        float el0 = 0.f, er0 = 0.f, el1 = 0.f, er1 = 0.f;
        #pragma unroll
        for (int j = 0; j < 4; j++) {
            int c = col0 + j * 8 + gc;
            float a0 = __ldg(alr + c), a1 = __ldg(alr + c + 1);
            float q0 = __ldg(arr + c), q1 = __ldg(arr + c + 1);
            *(float2*)(r0p + j * 8) = make_float2(acc[i][j][0], acc[i][j][1]);
            *(float2*)(r1p + j * 8) = make_float2(acc[i][j][2], acc[i][j][3]);
            el0 = fmaf(acc[i][j][0], a0, fmaf(acc[i][j][1], a1, el0));
            er0 = fmaf(acc[i][j][0], q0, fmaf(acc[i][j][1], q1, er0));
            el1 = fmaf(acc[i][j][2], a0, fmaf(acc[i][j][3], a1, el1));
            er1 = fmaf(acc[i][j][2], q0, fmaf(acc[i][j][3], q1, er1));
        }
        #pragma unroll
        for (int o = 1; o <= 2; o <<= 1) {
            el0 += __shfl_xor_sync(0xFFFFFFFFu, el0, o);
            er0 += __shfl_xor_sync(0xFFFFFFFFu, er0, o);
            el1 += __shfl_xor_sync(0xFFFFFFFFu, el1, o);
            er1 += __shfl_xor_sync(0xFFFFFFFFu, er1, o);
        }
        if ((lane & 3) == 0) {
            int r0 = row0 + i * 16 + gr;
            atomicAdd(&elb[r0], el0);
            atomicAdd(&erb[r0], er0);
            atomicAdd(&elb[r0 + 8], el1);
            atomicAdd(&erb[r0 + 8], er1);
        }
    }
}

// ---------------- CSR build: histogram, 3-step scan, fill ------------------
__global__ void hist_kernel(const int* __restrict__ dst) {
    int i = blockIdx.x * blockDim.x + threadIdx.x;
    if (i >= N_REL * N_EDGES) return;
    int r = i / N_EDGES;
    atomicAdd(&g_deg[r * N_NODES + dst[i]], 1);
}

__global__ void scan1_kernel() {              // per-1024-block exclusive scan
    __shared__ int s[1024];
    int t = threadIdx.x;
    int g = blockIdx.x * 1024 + t;
    int own = g_deg[g];
    s[t] = own;
    __syncthreads();
    #pragma unroll
    for (int o = 1; o < 1024; o <<= 1) {
        int v = (t >= o) ? s[t - o] : 0;
        __syncthreads();
        s[t] += v;
        __syncthreads();
    }
    g_off[g] = s[t] - own;                    // exclusive within block
    if (t == 1023) g_blk[blockIdx.x] = s[t];  // block total
}

__global__ void scan2_kernel() {              // scan the 192 block totals
    __shared__ int s[SCAN_BLOCKS];
    int t = threadIdx.x;
    int own = (t < SCAN_BLOCKS) ? g_blk[t] : 0;
    if (t < SCAN_BLOCKS) s[t] = own;
    __syncthreads();
    for (int o = 1; o < SCAN_BLOCKS; o <<= 1) {
        int v = (t >= o && t < SCAN_BLOCKS) ? s[t - o] : 0;
        __syncthreads();
        if (t < SCAN_BLOCKS) s[t] += v;
        __syncthreads();
    }
    if (t < SCAN_BLOCKS) g_blk[t] = s[t] - own;   // exclusive block offsets
}

__global__ void scan3_kernel() {              // add block offsets; init cursors
    int g = blockIdx.x * 1024 + threadIdx.x;
    int v = g_off[g] + g_blk[blockIdx.x];
    g_off[g] = v;
    g_cur[g] = v;
    if (g == 0) g_off[NSEG] = N_REL * N_EDGES;
}

__global__ void fill_kernel(const int* __restrict__ src, const int* __restrict__ dst) {
    int i = blockIdx.x * blockDim.x + threadIdx.x;
    if (i >= N_REL * N_EDGES) return;
    int r = i / N_EDGES;
    int pos = atomicAdd(&g_cur[r * N_NODES + dst[i]], 1);
    g_srcs[pos] = src[i];
}

// ---------------- aggregation: warp per dst node, ALL relations ------------
// (rel,node) uniquely owned by one warp -> plain ld/add/st on out, no REDG.
__global__ __launch_bounds__(256) void agg_all_kernel(float* __restrict__ out) {
    int node = (blockIdx.x * blockDim.x + threadIdx.x) >> 5;
    int lane = threadIdx.x & 31;
    if (node >= N_NODES) return;

    float tot[8] = {0.f, 0.f, 0.f, 0.f, 0.f, 0.f, 0.f, 0.f};
    bool any = false;

    #pragma unroll
    for (int rel = 0; rel < N_REL; rel++) {
        const int base = rel * N_NODES;
        const int beg = g_off[base + node];
        const int end = g_off[base + node + 1];
        if (beg == end) continue;
        any = true;

        const float erd = g_er3[base + node];
        const float* zb = g_z3 + (size_t)rel * N_NODES * OUT_FEAT;
        const float* elb = g_el3 + base;

        float acc[8] = {0.f, 0.f, 0.f, 0.f, 0.f, 0.f, 0.f, 0.f};
        float denom = 0.f;

        for (int c = beg; c < end; c += 32) {
            int idx = c + lane;
            int s = 0;
            float w = 0.f;
            if (idx < end) {
                s = g_srcs[idx];
                float e = elb[s] + erd;
                e = e >= 0.f ? e : NEG_SLOPE * e;
                w = expf(e);
            }
            float ws = w;
            #pragma unroll
            for (int o = 16; o; o >>= 1) ws += __shfl_xor_sync(0xFFFFFFFFu, ws, o);
            denom += ws;

            int cnt = min(32, end - c);
            for (int j = 0; j < cnt; j++) {
                int   sj = __shfl_sync(0xFFFFFFFFu, s, j);
                float wj = __shfl_sync(0xFFFFFFFFu, w, j);
                const float4* zp = (const float4*)(zb + (size_t)sj * OUT_FEAT) + lane * 2;
                float4 u = zp[0], v = zp[1];
                acc[0] = fmaf(wj, u.x, acc[0]); acc[1] = fmaf(wj, u.y, acc[1]);
                acc[2] = fmaf(wj, u.z, acc[2]); acc[3] = fmaf(wj, u.w, acc[3]);
                acc[4] = fmaf(wj, v.x, acc[4]); acc[5] = fmaf(wj, v.y, acc[5]);
                acc[6] = fmaf(wj, v.z, acc[6]); acc[7] = fmaf(wj, v.w, acc[7]);
            }
        }

        const float inv = 1.f / (denom + EPS);
        #pragma unroll
        for (int k = 0; k < 8; k++) tot[k] = fmaf(acc[k], inv, tot[k]);
    }

    if (!any) return;
    float4* op = (float4*)(out + (size_t)node * OUT_FEAT) + lane * 2;
    float4 o0 = op[0], o1 = op[1];
    o0.x += tot[0]; o0.y += tot[1]; o0.z += tot[2]; o0.w += tot[3];
    o1.x += tot[4]; o1.y += tot[5]; o1.z += tot[6]; o1.w += tot[7];
    op[0] = o0; op[1] = o1;
}

// ---------------- launch ----------------------------------------------------
extern "C" void kernel_launch(void* const* d_in, const int* in_sizes, int n_in,
                              void* d_out, int out_size) {
    const float* h   = (const float*)d_in[0];
    const float* W   = (const float*)d_in[1];
    const float* al  = (const float*)d_in[2];
    const float* ar  = (const float*)d_in[3];
    const float* b   = (const float*)d_in[4];
    const int*   src = (const int*)d_in[5];
    const int*   dst = (const int*)d_in[6];
    float*       out = (float*)d_out;

    cudaFuncSetAttribute(gemm_tf32_kernel,
                         cudaFuncAttributeMaxDynamicSharedMemorySize, GEMM_SMEM_BYTES);

    // launches 1..3; GEMM stays launch #4 (ncu capture slot)
    init_out_kernel<<<(N_NODES * OUT_FEAT + 255) / 256, 256>>>(b, out);
    preround_h_kernel<<<((N_NODES * (IN_FEAT / 4)) + 255) / 256, 256>>>(h);
    preround_w_kernel<<<(N_REL * IN_FEAT * OUT_FEAT / 4 + 255) / 256, 256>>>(W);

    dim3 gemm_grid(OUT_FEAT / GBN, N_NODES / GBM, N_REL);
    gemm_tf32_kernel<<<gemm_grid, 256, GEMM_SMEM_BYTES>>>(al, ar);

    int eg = (N_REL * N_EDGES + 255) / 256;
    hist_kernel<<<eg, 256>>>(dst);
    scan1_kernel<<<SCAN_BLOCKS, 1024>>>();
    scan2_kernel<<<1, 256>>>();
    scan3_kernel<<<SCAN_BLOCKS, 1024>>>();
    fill_kernel<<<eg, 256>>>(src, dst);

    agg_all_kernel<<<(N_NODES * 32) / 256, 256>>>(out);
}

// round 11
// speedup vs baseline: 1.1378x; 1.1378x over previous
#include <cuda_runtime.h>
#include <cuda_fp16.h>
#include <cstdint>

#define N_NODES 65536
#define IN_FEAT 512
#define OUT_FEAT 256
#define N_REL 3
#define N_EDGES 500000
#define NEG_SLOPE 0.2f
#define EPS 1e-9f
#define NSEG (N_REL * N_NODES)          // 196608 segments
#define SCAN_BLOCKS (NSEG / 1024)       // 192

// ---------------- scratch (static device globals; no allocs allowed) ---------
__device__ float  g_ha[(size_t)N_NODES * IN_FEAT];             // tf32-rounded h
__device__ float  g_Wp[(size_t)N_REL * IN_FEAT * OUT_FEAT];    // tf32-rounded W
__device__ __half g_zh[(size_t)N_REL * N_NODES * OUT_FEAT];    // 96 MB z (fp16)
__device__ float  g_el3[NSEG];
__device__ float  g_er3[NSEG];
__device__ int    g_deg[NSEG];
__device__ int    g_off[NSEG + 1];
__device__ int    g_cur[NSEG];
__device__ int    g_blk[SCAN_BLOCKS];
__device__ int    g_srcs[(size_t)N_REL * N_EDGES];             // dst-sorted src ids

__device__ __forceinline__ uint32_t smem_u32(const void* p) {
    return (uint32_t)__cvta_generic_to_shared(p);
}
__device__ __forceinline__ void cp_async16(uint32_t saddr, const void* gaddr) {
    asm volatile("cp.async.cg.shared.global [%0], [%1], 16;" :: "r"(saddr), "l"(gaddr));
}
__device__ __forceinline__ uint32_t rna_tf32(uint32_t x) {
    asm("cvt.rna.tf32.f32 %0, %0;" : "+r"(x));
    return x;
}

// ---------------- init: out bias + zero accumulators/counters --------------
__global__ void init_out_kernel(const float* __restrict__ b, float* __restrict__ out) {
    int i = blockIdx.x * blockDim.x + threadIdx.x;
    if (i < NSEG) {
        g_el3[i] = 0.f;
        g_er3[i] = 0.f;
        g_deg[i] = 0;
    }
    if (i >= N_NODES * OUT_FEAT) return;
    int f = i & (OUT_FEAT - 1);
    out[i] = b[f] + b[OUT_FEAT + f] + b[2 * OUT_FEAT + f];
}

// ---------------- pre-round h to tf32 (RNA) once ---------------------------
__global__ void preround_h_kernel(const float* __restrict__ h) {
    size_t i = (size_t)blockIdx.x * blockDim.x + threadIdx.x;
    size_t n4 = (size_t)N_NODES * IN_FEAT / 4;
    if (i >= n4) return;
    uint4 v = ((const uint4*)h)[i];
    v.x = rna_tf32(v.x); v.y = rna_tf32(v.y);
    v.z = rna_tf32(v.z); v.w = rna_tf32(v.w);
    ((uint4*)g_ha)[i] = v;
}

// ---------------- pre-round ALL relations' W -------------------------------
__global__ void preround_w_kernel(const float* __restrict__ W) {
    int i = blockIdx.x * blockDim.x + threadIdx.x;
    int n4 = N_REL * IN_FEAT * OUT_FEAT / 4;
    if (i >= n4) return;
    uint4 v = ((const uint4*)W)[i];
    v.x = rna_tf32(v.x); v.y = rna_tf32(v.y);
    v.z = rna_tf32(v.z); v.w = rna_tf32(v.w);
    ((uint4*)g_Wp)[i] = v;
}

// ---------------- TF32 GEMM, all relations, fused logit epilogue -----------
// (R9 mainloop verbatim — the R10 address-hoist regressed it; reverted.)
#define GBM 128
#define GBN 128
#define GBK 32
#define LDA 36
#define LDB 136
#define A_STAGE (GBM * LDA)
#define B_STAGE (GBK * LDB)
#define STAGE_FLOATS (A_STAGE + B_STAGE)
#define NSTAGES 3
#define GEMM_SMEM_BYTES (NSTAGES * STAGE_FLOATS * 4)
#define KITERS (IN_FEAT / GBK)

__global__ __launch_bounds__(256, 2) void gemm_tf32_kernel(const float* __restrict__ al,
                                                           const float* __restrict__ ar) {
    extern __shared__ float smem[];
    const int tid  = threadIdx.x;
    const int bx   = blockIdx.x;
    const int by   = blockIdx.y;
    const int rel  = blockIdx.z;
    const int warp = tid >> 5, lane = tid & 31;
    const int wm = warp >> 2;
    const int wn = warp & 3;

    const int a_row_off = (lane & 7) + ((lane >> 3) & 1) * 8;
    const int a_col_off = ((lane >> 4) & 1) * 4;
    const int b_k_off = lane & 3;
    const int b_n_off = lane >> 2;

    const float* Ag0 = g_ha + (size_t)(by * GBM) * IN_FEAT;
    const float* Bg0 = g_Wp + (size_t)rel * IN_FEAT * OUT_FEAT + bx * GBN;
    const float* alr = al + rel * OUT_FEAT;
    const float* arr = ar + rel * OUT_FEAT;

    float acc[4][4][4];
    #pragma unroll
    for (int i = 0; i < 4; i++)
        #pragma unroll
        for (int j = 0; j < 4; j++)
            #pragma unroll
            for (int v = 0; v < 4; v++) acc[i][j][v] = 0.f;

    auto load_stage = [&](int kt, int s) {
        float* As = smem + s * STAGE_FLOATS;
        float* Bs = As + A_STAGE;
        const float* Ag = Ag0 + kt * GBK;
        const float* Bg = Bg0 + (size_t)(kt * GBK) * OUT_FEAT;
        #pragma unroll
        for (int i = 0; i < 4; i++) {
            int q = tid + i * 256;
            int r = q >> 3, c = q & 7;
            cp_async16(smem_u32(As + r * LDA + c * 4), Ag + (size_t)r * IN_FEAT + c * 4);
        }
        #pragma unroll
        for (int i = 0; i < 4; i++) {
            int q = tid + i * 256;
            int r = q >> 5, c = q & 31;
            cp_async16(smem_u32(Bs + r * LDB + c * 4), Bg + (size_t)r * OUT_FEAT + c * 4);
        }
    };

    load_stage(0, 0);
    asm volatile("cp.async.commit_group;");
    load_stage(1, 1);
    asm volatile("cp.async.commit_group;");
    load_stage(2, 2);
    asm volatile("cp.async.commit_group;");

    int slot = 0;
    for (int kt = 0; kt < KITERS; kt++) {
        asm volatile("cp.async.wait_group 2;");
        __syncthreads();

        const float* As = smem + slot * STAGE_FLOATS;
        const float* Bs = As + A_STAGE;

        #pragma unroll
        for (int k8 = 0; k8 < GBK / 8; k8++) {
            uint32_t a[4][4];
            #pragma unroll
            for (int i = 0; i < 4; i++) {
                const float* p = As + (wm * 64 + i * 16 + a_row_off) * LDA + k8 * 8 + a_col_off;
                uint32_t addr = smem_u32(p);
                asm volatile("ldmatrix.sync.aligned.m8n8.x4.shared.b16 {%0,%1,%2,%3}, [%4];"
                             : "=r"(a[i][0]), "=r"(a[i][1]), "=r"(a[i][2]), "=r"(a[i][3])
                             : "r"(addr));
            }
            uint32_t bf[4][2];
            #pragma unroll
            for (int j = 0; j < 4; j++) {
                const float* p = Bs + (k8 * 8 + b_k_off) * LDB + wn * 32 + j * 8 + b_n_off;
                bf[j][0] = __float_as_uint(p[0]);
                bf[j][1] = __float_as_uint(p[4 * LDB]);
            }
            #pragma unroll
            for (int i = 0; i < 4; i++)
                #pragma unroll
                for (int j = 0; j < 4; j++) {
                    asm volatile(
                        "mma.sync.aligned.m16n8k8.row.col.f32.tf32.tf32.f32 "
                        "{%0,%1,%2,%3}, {%4,%5,%6,%7}, {%8,%9}, {%0,%1,%2,%3};"
                        : "+f"(acc[i][j][0]), "+f"(acc[i][j][1]),
                          "+f"(acc[i][j][2]), "+f"(acc[i][j][3])
                        : "r"(a[i][0]), "r"(a[i][1]), "r"(a[i][2]), "r"(a[i][3]),
                          "r"(bf[j][0]), "r"(bf[j][1]));
                }
        }
        __syncthreads();
        if (kt + 3 < KITERS) load_stage(kt + 3, slot);
        asm volatile("cp.async.commit_group;");
        slot = (slot == NSTAGES - 1) ? 0 : slot + 1;
    }

    // ------- epilogue: write z as fp16, fused el/er dots (fp32) ------------
    __half* zb = g_zh + (size_t)rel * N_NODES * OUT_FEAT;
    float* elb = g_el3 + rel * N_NODES;
    float* erb = g_er3 + rel * N_NODES;
    const int row0 = by * GBM + wm * 64;
    const int col0 = bx * GBN + wn * 32;
    const int gr = lane >> 2;
    const int gc = (lane & 3) * 2;
    #pragma unroll
    for (int i = 0; i < 4; i++) {
        __half* r0p = zb + (size_t)(row0 + i * 16 + gr) * OUT_FEAT + col0 + gc;
        __half* r1p = r0p + (size_t)8 * OUT_FEAT;
        float el0 = 0.f, er0 = 0.f, el1 = 0.f, er1 = 0.f;
        #pragma unroll
        for (int j = 0; j < 4; j++) {
            int c = col0 + j * 8 + gc;
            float a0 = __ldg(alr + c), a1 = __ldg(alr + c + 1);
            float q0 = __ldg(arr + c), q1 = __ldg(arr + c + 1);
            *(__half2*)(r0p + j * 8) =
                __floats2half2_rn(acc[i][j][0], acc[i][j][1]);
            *(__half2*)(r1p + j * 8) =
                __floats2half2_rn(acc[i][j][2], acc[i][j][3]);
            el0 = fmaf(acc[i][j][0], a0, fmaf(acc[i][j][1], a1, el0));
            er0 = fmaf(acc[i][j][0], q0, fmaf(acc[i][j][1], q1, er0));
            el1 = fmaf(acc[i][j][2], a0, fmaf(acc[i][j][3], a1, el1));
            er1 = fmaf(acc[i][j][2], q0, fmaf(acc[i][j][3], q1, er1));
        }
        #pragma unroll
        for (int o = 1; o <= 2; o <<= 1) {
            el0 += __shfl_xor_sync(0xFFFFFFFFu, el0, o);
            er0 += __shfl_xor_sync(0xFFFFFFFFu, er0, o);
            el1 += __shfl_xor_sync(0xFFFFFFFFu, el1, o);
            er1 += __shfl_xor_sync(0xFFFFFFFFu, er1, o);
        }
        if ((lane & 3) == 0) {
            int r0 = row0 + i * 16 + gr;
            atomicAdd(&elb[r0], el0);
            atomicAdd(&erb[r0], er0);
            atomicAdd(&elb[r0 + 8], el1);
            atomicAdd(&erb[r0 + 8], er1);
        }
    }
}

// ---------------- CSR build: histogram, 3-step scan, fill ------------------
__global__ void hist_kernel(const int* __restrict__ dst) {
    int i = blockIdx.x * blockDim.x + threadIdx.x;
    if (i >= N_REL * N_EDGES) return;
    int r = i / N_EDGES;
    atomicAdd(&g_deg[r * N_NODES + dst[i]], 1);
}

__global__ void scan1_kernel() {              // per-1024-block exclusive scan
    __shared__ int s[1024];
    int t = threadIdx.x;
    int g = blockIdx.x * 1024 + t;
    int own = g_deg[g];
    s[t] = own;
    __syncthreads();
    #pragma unroll
    for (int o = 1; o < 1024; o <<= 1) {
        int v = (t >= o) ? s[t - o] : 0;
        __syncthreads();
        s[t] += v;
        __syncthreads();
    }
    g_off[g] = s[t] - own;
    if (t == 1023) g_blk[blockIdx.x] = s[t];
}

__global__ void scan2_kernel() {              // scan the 192 block totals
    __shared__ int s[SCAN_BLOCKS];
    int t = threadIdx.x;
    int own = (t < SCAN_BLOCKS) ? g_blk[t] : 0;
    if (t < SCAN_BLOCKS) s[t] = own;
    __syncthreads();
    for (int o = 1; o < SCAN_BLOCKS; o <<= 1) {
        int v = (t >= o && t < SCAN_BLOCKS) ? s[t - o] : 0;
        __syncthreads();
        if (t < SCAN_BLOCKS) s[t] += v;
        __syncthreads();
    }
    if (t < SCAN_BLOCKS) g_blk[t] = s[t] - own;
}

__global__ void scan3_kernel() {              // add block offsets; init cursors
    int g = blockIdx.x * 1024 + threadIdx.x;
    int v = g_off[g] + g_blk[blockIdx.x];
    g_off[g] = v;
    g_cur[g] = v;
    if (g == 0) g_off[NSEG] = N_REL * N_EDGES;
}

__global__ void fill_kernel(const int* __restrict__ src, const int* __restrict__ dst) {
    int i = blockIdx.x * blockDim.x + threadIdx.x;
    if (i >= N_REL * N_EDGES) return;
    int r = i / N_EDGES;
    int pos = atomicAdd(&g_cur[r * N_NODES + dst[i]], 1);
    g_srcs[pos] = src[i];
}

// ---------------- aggregation: warp per dst node, ALL relations ------------
// z gathered as fp16 (16B per lane per edge); accum fp32; plain st on out.
__global__ __launch_bounds__(256) void agg_all_kernel(float* __restrict__ out) {
    int node = (blockIdx.x * blockDim.x + threadIdx.x) >> 5;
    int lane = threadIdx.x & 31;
    if (node >= N_NODES) return;

    float tot[8] = {0.f, 0.f, 0.f, 0.f, 0.f, 0.f, 0.f, 0.f};
    bool any = false;

    #pragma unroll
    for (int rel = 0; rel < N_REL; rel++) {
        const int base = rel * N_NODES;
        const int beg = g_off[base + node];
        const int end = g_off[base + node + 1];
        if (beg == end) continue;
        any = true;

        const float erd = g_er3[base + node];
        const __half* zb = g_zh + (size_t)rel * N_NODES * OUT_FEAT;
        const float* elb = g_el3 + base;

        float acc[8] = {0.f, 0.f, 0.f, 0.f, 0.f, 0.f, 0.f, 0.f};
        float denom = 0.f;

        for (int c = beg; c < end; c += 32) {
            int idx = c + lane;
            int s = 0;
            float w = 0.f;
            if (idx < end) {
                s = g_srcs[idx];
                float e = elb[s] + erd;
                e = e >= 0.f ? e : NEG_SLOPE * e;
                w = expf(e);
            }
            float ws = w;
            #pragma unroll
            for (int o = 16; o; o >>= 1) ws += __shfl_xor_sync(0xFFFFFFFFu, ws, o);
            denom += ws;

            int cnt = min(32, end - c);
            for (int j = 0; j < cnt; j++) {
                int   sj = __shfl_sync(0xFFFFFFFFu, s, j);
                float wj = __shfl_sync(0xFFFFFFFFu, w, j);
                const uint4* zp = (const uint4*)(zb + (size_t)sj * OUT_FEAT);
                uint4 p = zp[lane];                           // 8 halves
                float2 f0 = __half22float2(*(__half2*)&p.x);
                float2 f1 = __half22float2(*(__half2*)&p.y);
                float2 f2 = __half22float2(*(__half2*)&p.z);
                float2 f3 = __half22float2(*(__half2*)&p.w);
                acc[0] = fmaf(wj, f0.x, acc[0]); acc[1] = fmaf(wj, f0.y, acc[1]);
                acc[2] = fmaf(wj, f1.x, acc[2]); acc[3] = fmaf(wj, f1.y, acc[3]);
                acc[4] = fmaf(wj, f2.x, acc[4]); acc[5] = fmaf(wj, f2.y, acc[5]);
                acc[6] = fmaf(wj, f3.x, acc[6]); acc[7] = fmaf(wj, f3.y, acc[7]);
            }
        }

        const float inv = 1.f / (denom + EPS);
        #pragma unroll
        for (int k = 0; k < 8; k++) tot[k] = fmaf(acc[k], inv, tot[k]);
    }

    if (!any) return;
    float4* op = (float4*)(out + (size_t)node * OUT_FEAT) + lane * 2;
    float4 o0 = op[0], o1 = op[1];
    o0.x += tot[0]; o0.y += tot[1]; o0.z += tot[2]; o0.w += tot[3];
    o1.x += tot[4]; o1.y += tot[5]; o1.z += tot[6]; o1.w += tot[7];
    op[0] = o0; op[1] = o1;
}

// ---------------- launch ----------------------------------------------------
extern "C" void kernel_launch(void* const* d_in, const int* in_sizes, int n_in,
                              void* d_out, int out_size) {
    const float* h   = (const float*)d_in[0];
    const float* W   = (const float*)d_in[1];
    const float* al  = (const float*)d_in[2];
    const float* ar  = (const float*)d_in[3];
    const float* b   = (const float*)d_in[4];
    const int*   src = (const int*)d_in[5];
    const int*   dst = (const int*)d_in[6];
    float*       out = (float*)d_out;

    cudaFuncSetAttribute(gemm_tf32_kernel,
                         cudaFuncAttributeMaxDynamicSharedMemorySize, GEMM_SMEM_BYTES);

    // launches 1..3; GEMM stays launch #4 (ncu capture slot)
    init_out_kernel<<<(N_NODES * OUT_FEAT + 255) / 256, 256>>>(b, out);
    preround_h_kernel<<<((N_NODES * (IN_FEAT / 4)) + 255) / 256, 256>>>(h);
    preround_w_kernel<<<(N_REL * IN_FEAT * OUT_FEAT / 4 + 255) / 256, 256>>>(W);

    dim3 gemm_grid(OUT_FEAT / GBN, N_NODES / GBM, N_REL);
    gemm_tf32_kernel<<<gemm_grid, 256, GEMM_SMEM_BYTES>>>(al, ar);

    int eg = (N_REL * N_EDGES + 255) / 256;
    hist_kernel<<<eg, 256>>>(dst);
    scan1_kernel<<<SCAN_BLOCKS, 1024>>>();
    scan2_kernel<<<1, 256>>>();
    scan3_kernel<<<SCAN_BLOCKS, 1024>>>();
    fill_kernel<<<eg, 256>>>(src, dst);

    agg_all_kernel<<<(N_NODES * 32) / 256, 256>>>(out);
}

// round 12
// speedup vs baseline: 1.5295x; 1.3442x over previous
#include <cuda_runtime.h>
#include <cuda_fp16.h>
#include <cstdint>

#define N_NODES 65536
#define IN_FEAT 512
#define OUT_FEAT 256
#define N_REL 3
#define N_EDGES 500000
#define NEG_SLOPE 0.2f
#define EPS 1e-9f
#define NSEG (N_REL * N_NODES)          // 196608 segments
#define SCAN_BLOCKS (NSEG / 1024)       // 192

// ---------------- scratch (static device globals; no allocs allowed) ---------
__device__ __half g_hh[(size_t)N_NODES * IN_FEAT];             // 64 MB fp16 h
__device__ __half g_Wth[(size_t)N_REL * OUT_FEAT * IN_FEAT];   // fp16 W^T [rel][n][k]
__device__ __half g_zh[(size_t)N_REL * N_NODES * OUT_FEAT];    // 96 MB z (fp16)
__device__ float  g_el3[NSEG];
__device__ float  g_er3[NSEG];
__device__ int    g_deg[NSEG];
__device__ int    g_off[NSEG + 1];
__device__ int    g_cur[NSEG];
__device__ int    g_blk[SCAN_BLOCKS];
__device__ int    g_srcs[(size_t)N_REL * N_EDGES];             // dst-sorted src ids

__device__ __forceinline__ uint32_t smem_u32(const void* p) {
    return (uint32_t)__cvta_generic_to_shared(p);
}
__device__ __forceinline__ void cp_async16(uint32_t saddr, const void* gaddr) {
    asm volatile("cp.async.cg.shared.global [%0], [%1], 16;" :: "r"(saddr), "l"(gaddr));
}

// ---------------- init: out bias + zero accumulators/counters --------------
__global__ void init_out_kernel(const float* __restrict__ b, float* __restrict__ out) {
    int i = blockIdx.x * blockDim.x + threadIdx.x;
    if (i < NSEG) {
        g_el3[i] = 0.f;
        g_er3[i] = 0.f;
        g_deg[i] = 0;
    }
    if (i >= N_NODES * OUT_FEAT) return;
    int f = i & (OUT_FEAT - 1);
    out[i] = b[f] + b[OUT_FEAT + f] + b[2 * OUT_FEAT + f];
}

// ---------------- h -> fp16 (RN) once --------------------------------------
__global__ void h2h_kernel(const float* __restrict__ h) {
    size_t i = (size_t)blockIdx.x * blockDim.x + threadIdx.x;
    size_t n8 = (size_t)N_NODES * IN_FEAT / 8;
    if (i >= n8) return;
    float4 v0 = ((const float4*)h)[2 * i];
    float4 v1 = ((const float4*)h)[2 * i + 1];
    __half2 o[4];
    o[0] = __floats2half2_rn(v0.x, v0.y);
    o[1] = __floats2half2_rn(v0.z, v0.w);
    o[2] = __floats2half2_rn(v1.x, v1.y);
    o[3] = __floats2half2_rn(v1.z, v1.w);
    ((uint4*)g_hh)[i] = *(uint4*)o;
}

// ---------------- W -> fp16 transposed: g_Wth[rel][n][k] --------------------
__global__ void wt_kernel(const float* __restrict__ W) {
    __shared__ float t[32][33];
    int rel = blockIdx.z;
    const float* Wr = W + (size_t)rel * IN_FEAT * OUT_FEAT;
    __half* Wt = g_Wth + (size_t)rel * IN_FEAT * OUT_FEAT;
    int k0 = blockIdx.y * 32, n0 = blockIdx.x * 32;
    int tx = threadIdx.x, ty = threadIdx.y;    // 32 x 8
    #pragma unroll
    for (int i = 0; i < 4; i++)
        t[ty + 8 * i][tx] = Wr[(size_t)(k0 + ty + 8 * i) * OUT_FEAT + n0 + tx];
    __syncthreads();
    #pragma unroll
    for (int i = 0; i < 4; i++)
        Wt[(size_t)(n0 + ty + 8 * i) * IN_FEAT + k0 + tx] =
            __float2half_rn(t[tx][ty + 8 * i]);
}

// ---------------- FP16 tensor-core GEMM + fused logit epilogue -------------
// CTA 128x128x64(halves), 8 warps (2x4), warp m64n32, mma.m16n8k16.f16, occ 2.
#define GBM 128
#define GBN 128
#define GBK 64                      // K halves per stage
#define RS 72                       // smem row stride in halves (144 B, conflict-free)
#define A_STAGE_H (GBM * RS)
#define B_STAGE_H (GBN * RS)
#define STAGE_H (A_STAGE_H + B_STAGE_H)
#define NSTAGES 3
#define GEMM_SMEM_BYTES (NSTAGES * STAGE_H * 2)   // 110592 B
#define KITERS (IN_FEAT / GBK)      // 8

__global__ __launch_bounds__(256, 2) void gemm_f16_kernel(const float* __restrict__ al,
                                                          const float* __restrict__ ar) {
    extern __shared__ __half smem[];
    const int tid  = threadIdx.x;
    const int bx   = blockIdx.x;            // N tile (0..1)
    const int by   = blockIdx.y;            // M tile (0..511)
    const int rel  = blockIdx.z;
    const int warp = tid >> 5, lane = tid & 31;
    const int wm = warp >> 2;
    const int wn = warp & 3;

    // ldmatrix lane addressing
    const int a_row = wm * 64 + (lane & 7) + ((lane >> 3) & 1) * 8;
    const int a_col = ((lane >> 4) & 1) * 8;
    const int b_row = wn * 32 + (lane & 7) + ((lane >> 4) & 1) * 8;
    const int b_col = ((lane >> 3) & 1) * 8;

    const __half* Ag0 = g_hh + (size_t)(by * GBM) * IN_FEAT;
    const __half* Bg0 = g_Wth + (size_t)rel * IN_FEAT * OUT_FEAT
                              + (size_t)(bx * GBN) * IN_FEAT;
    const float* alr = al + rel * OUT_FEAT;
    const float* arr = ar + rel * OUT_FEAT;

    float acc[4][4][4];
    #pragma unroll
    for (int i = 0; i < 4; i++)
        #pragma unroll
        for (int j = 0; j < 4; j++)
            #pragma unroll
            for (int v = 0; v < 4; v++) acc[i][j][v] = 0.f;

    auto load_stage = [&](int kt, int s) {
        __half* As = smem + s * STAGE_H;
        __half* Bs = As + A_STAGE_H;
        const __half* Ag = Ag0 + kt * GBK;
        const __half* Bg = Bg0 + kt * GBK;
        #pragma unroll
        for (int i = 0; i < 4; i++) {
            int q = tid + i * 256;             // 128 rows x 8 chunks of 16B
            int r = q >> 3, c = q & 7;
            cp_async16(smem_u32(As + r * RS + c * 8), Ag + (size_t)r * IN_FEAT + c * 8);
        }
        #pragma unroll
        for (int i = 0; i < 4; i++) {
            int q = tid + i * 256;
            int r = q >> 3, c = q & 7;
            cp_async16(smem_u32(Bs + r * RS + c * 8), Bg + (size_t)r * IN_FEAT + c * 8);
        }
    };

    load_stage(0, 0);
    asm volatile("cp.async.commit_group;");
    load_stage(1, 1);
    asm volatile("cp.async.commit_group;");
    load_stage(2, 2);
    asm volatile("cp.async.commit_group;");

    int slot = 0;
    for (int kt = 0; kt < KITERS; kt++) {
        asm volatile("cp.async.wait_group 2;");
        __syncthreads();

        const __half* As = smem + slot * STAGE_H;
        const __half* Bs = As + A_STAGE_H;

        #pragma unroll
        for (int k16 = 0; k16 < GBK / 16; k16++) {
            uint32_t a[4][4];
            #pragma unroll
            for (int i = 0; i < 4; i++) {
                uint32_t addr = smem_u32(As + (a_row + i * 16) * RS + k16 * 16 + a_col);
                asm volatile("ldmatrix.sync.aligned.m8n8.x4.shared.b16 {%0,%1,%2,%3}, [%4];"
                             : "=r"(a[i][0]), "=r"(a[i][1]), "=r"(a[i][2]), "=r"(a[i][3])
                             : "r"(addr));
            }
            uint32_t bf[4][2];
            #pragma unroll
            for (int jj = 0; jj < 2; jj++) {
                uint32_t addr = smem_u32(Bs + (b_row + jj * 16) * RS + k16 * 16 + b_col);
                asm volatile("ldmatrix.sync.aligned.m8n8.x4.shared.b16 {%0,%1,%2,%3}, [%4];"
                             : "=r"(bf[2*jj][0]), "=r"(bf[2*jj][1]),
                               "=r"(bf[2*jj+1][0]), "=r"(bf[2*jj+1][1])
                             : "r"(addr));
            }
            #pragma unroll
            for (int i = 0; i < 4; i++)
                #pragma unroll
                for (int j = 0; j < 4; j++) {
                    asm volatile(
                        "mma.sync.aligned.m16n8k16.row.col.f32.f16.f16.f32 "
                        "{%0,%1,%2,%3}, {%4,%5,%6,%7}, {%8,%9}, {%0,%1,%2,%3};"
                        : "+f"(acc[i][j][0]), "+f"(acc[i][j][1]),
                          "+f"(acc[i][j][2]), "+f"(acc[i][j][3])
                        : "r"(a[i][0]), "r"(a[i][1]), "r"(a[i][2]), "r"(a[i][3]),
                          "r"(bf[j][0]), "r"(bf[j][1]));
                }
        }
        __syncthreads();
        if (kt + 3 < KITERS) load_stage(kt + 3, slot);
        asm volatile("cp.async.commit_group;");
        slot = (slot == NSTAGES - 1) ? 0 : slot + 1;
    }

    // ------- epilogue: write z fp16, fused el/er dots (fp32), reset --------
    __half* zb = g_zh + (size_t)rel * N_NODES * OUT_FEAT;
    float* elb = g_el3 + rel * N_NODES;
    float* erb = g_er3 + rel * N_NODES;
    const int row0 = by * GBM + wm * 64;
    const int col0 = bx * GBN + wn * 32;
    const int gr = lane >> 2;
    const int gc = (lane & 3) * 2;
    #pragma unroll
    for (int i = 0; i < 4; i++) {
        __half* r0p = zb + (size_t)(row0 + i * 16 + gr) * OUT_FEAT + col0 + gc;
        __half* r1p = r0p + (size_t)8 * OUT_FEAT;
        float el0 = 0.f, er0 = 0.f, el1 = 0.f, er1 = 0.f;
        #pragma unroll
        for (int j = 0; j < 4; j++) {
            int c = col0 + j * 8 + gc;
            float a0 = __ldg(alr + c), a1 = __ldg(alr + c + 1);
            float q0 = __ldg(arr + c), q1 = __ldg(arr + c + 1);
            *(__half2*)(r0p + j * 8) = __floats2half2_rn(acc[i][j][0], acc[i][j][1]);
            *(__half2*)(r1p + j * 8) = __floats2half2_rn(acc[i][j][2], acc[i][j][3]);
            el0 = fmaf(acc[i][j][0], a0, fmaf(acc[i][j][1], a1, el0));
            er0 = fmaf(acc[i][j][0], q0, fmaf(acc[i][j][1], q1, er0));
            el1 = fmaf(acc[i][j][2], a0, fmaf(acc[i][j][3], a1, el1));
            er1 = fmaf(acc[i][j][2], q0, fmaf(acc[i][j][3], q1, er1));
        }
        #pragma unroll
        for (int o = 1; o <= 2; o <<= 1) {
            el0 += __shfl_xor_sync(0xFFFFFFFFu, el0, o);
            er0 += __shfl_xor_sync(0xFFFFFFFFu, er0, o);
            el1 += __shfl_xor_sync(0xFFFFFFFFu, el1, o);
            er1 += __shfl_xor_sync(0xFFFFFFFFu, er1, o);
        }
        if ((lane & 3) == 0) {
            int r0 = row0 + i * 16 + gr;
            atomicAdd(&elb[r0], el0);
            atomicAdd(&erb[r0], er0);
            atomicAdd(&elb[r0 + 8], el1);
            atomicAdd(&erb[r0 + 8], er1);
        }
    }
}

// ---------------- CSR build: histogram, 3-step scan, fill ------------------
__global__ void hist_kernel(const int* __restrict__ dst) {
    int i = blockIdx.x * blockDim.x + threadIdx.x;
    if (i >= N_REL * N_EDGES) return;
    int r = i / N_EDGES;
    atomicAdd(&g_deg[r * N_NODES + dst[i]], 1);
}

__global__ void scan1_kernel() {
    __shared__ int s[1024];
    int t = threadIdx.x;
    int g = blockIdx.x * 1024 + t;
    int own = g_deg[g];
    s[t] = own;
    __syncthreads();
    #pragma unroll
    for (int o = 1; o < 1024; o <<= 1) {
        int v = (t >= o) ? s[t - o] : 0;
        __syncthreads();
        s[t] += v;
        __syncthreads();
    }
    g_off[g] = s[t] - own;
    if (t == 1023) g_blk[blockIdx.x] = s[t];
}

__global__ void scan2_kernel() {
    __shared__ int s[SCAN_BLOCKS];
    int t = threadIdx.x;
    int own = (t < SCAN_BLOCKS) ? g_blk[t] : 0;
    if (t < SCAN_BLOCKS) s[t] = own;
    __syncthreads();
    for (int o = 1; o < SCAN_BLOCKS; o <<= 1) {
        int v = (t >= o && t < SCAN_BLOCKS) ? s[t - o] : 0;
        __syncthreads();
        if (t < SCAN_BLOCKS) s[t] += v;
        __syncthreads();
    }
    if (t < SCAN_BLOCKS) g_blk[t] = s[t] - own;
}

__global__ void scan3_kernel() {
    int g = blockIdx.x * 1024 + threadIdx.x;
    int v = g_off[g] + g_blk[blockIdx.x];
    g_off[g] = v;
    g_cur[g] = v;
    if (g == 0) g_off[NSEG] = N_REL * N_EDGES;
}

__global__ void fill_kernel(const int* __restrict__ src, const int* __restrict__ dst) {
    int i = blockIdx.x * blockDim.x + threadIdx.x;
    if (i >= N_REL * N_EDGES) return;
    int r = i / N_EDGES;
    int pos = atomicAdd(&g_cur[r * N_NODES + dst[i]], 1);
    g_srcs[pos] = src[i];
}

// ---------------- aggregation: warp per dst node, ALL relations ------------
__global__ __launch_bounds__(256) void agg_all_kernel(float* __restrict__ out) {
    int node = (blockIdx.x * blockDim.x + threadIdx.x) >> 5;
    int lane = threadIdx.x & 31;
    if (node >= N_NODES) return;

    float tot[8] = {0.f, 0.f, 0.f, 0.f, 0.f, 0.f, 0.f, 0.f};
    bool any = false;

    #pragma unroll
    for (int rel = 0; rel < N_REL; rel++) {
        const int base = rel * N_NODES;
        const int beg = g_off[base + node];
        const int end = g_off[base + node + 1];
        if (beg == end) continue;
        any = true;

        const float erd = g_er3[base + node];
        const __half* zb = g_zh + (size_t)rel * N_NODES * OUT_FEAT;
        const float* elb = g_el3 + base;

        float acc[8] = {0.f, 0.f, 0.f, 0.f, 0.f, 0.f, 0.f, 0.f};
        float denom = 0.f;

        for (int c = beg; c < end; c += 32) {
            int idx = c + lane;
            int s = 0;
            float w = 0.f;
            if (idx < end) {
                s = g_srcs[idx];
                float e = elb[s] + erd;
                e = e >= 0.f ? e : NEG_SLOPE * e;
                w = expf(e);
            }
            float ws = w;
            #pragma unroll
            for (int o = 16; o; o >>= 1) ws += __shfl_xor_sync(0xFFFFFFFFu, ws, o);
            denom += ws;

            int cnt = min(32, end - c);
            for (int j = 0; j < cnt; j++) {
                int   sj = __shfl_sync(0xFFFFFFFFu, s, j);
                float wj = __shfl_sync(0xFFFFFFFFu, w, j);
                const uint4* zp = (const uint4*)(zb + (size_t)sj * OUT_FEAT);
                uint4 p = zp[lane];
                float2 f0 = __half22float2(*(__half2*)&p.x);
                float2 f1 = __half22float2(*(__half2*)&p.y);
                float2 f2 = __half22float2(*(__half2*)&p.z);
                float2 f3 = __half22float2(*(__half2*)&p.w);
                acc[0] = fmaf(wj, f0.x, acc[0]); acc[1] = fmaf(wj, f0.y, acc[1]);
                acc[2] = fmaf(wj, f1.x, acc[2]); acc[3] = fmaf(wj, f1.y, acc[3]);
                acc[4] = fmaf(wj, f2.x, acc[4]); acc[5] = fmaf(wj, f2.y, acc[5]);
                acc[6] = fmaf(wj, f3.x, acc[6]); acc[7] = fmaf(wj, f3.y, acc[7]);
            }
        }

        const float inv = 1.f / (denom + EPS);
        #pragma unroll
        for (int k = 0; k < 8; k++) tot[k] = fmaf(acc[k], inv, tot[k]);
    }

    if (!any) return;
    float4* op = (float4*)(out + (size_t)node * OUT_FEAT) + lane * 2;
    float4 o0 = op[0], o1 = op[1];
    o0.x += tot[0]; o0.y += tot[1]; o0.z += tot[2]; o0.w += tot[3];
    o1.x += tot[4]; o1.y += tot[5]; o1.z += tot[6]; o1.w += tot[7];
    op[0] = o0; op[1] = o1;
}

// ---------------- launch ----------------------------------------------------
extern "C" void kernel_launch(void* const* d_in, const int* in_sizes, int n_in,
                              void* d_out, int out_size) {
    const float* h   = (const float*)d_in[0];
    const float* W   = (const float*)d_in[1];
    const float* al  = (const float*)d_in[2];
    const float* ar  = (const float*)d_in[3];
    const float* b   = (const float*)d_in[4];
    const int*   src = (const int*)d_in[5];
    const int*   dst = (const int*)d_in[6];
    float*       out = (float*)d_out;

    cudaFuncSetAttribute(gemm_f16_kernel,
                         cudaFuncAttributeMaxDynamicSharedMemorySize, GEMM_SMEM_BYTES);

    // launches 1..3; GEMM stays launch #4 (ncu capture slot)
    init_out_kernel<<<(N_NODES * OUT_FEAT + 255) / 256, 256>>>(b, out);
    h2h_kernel<<<((N_NODES * (IN_FEAT / 8)) + 255) / 256, 256>>>(h);
    dim3 wt_grid(OUT_FEAT / 32, IN_FEAT / 32, N_REL);
    wt_kernel<<<wt_grid, dim3(32, 8)>>>(W);

    dim3 gemm_grid(OUT_FEAT / GBN, N_NODES / GBM, N_REL);   // (2, 512, 3)
    gemm_f16_kernel<<<gemm_grid, 256, GEMM_SMEM_BYTES>>>(al, ar);

    int eg = (N_REL * N_EDGES + 255) / 256;
    hist_kernel<<<eg, 256>>>(dst);
    scan1_kernel<<<SCAN_BLOCKS, 1024>>>();
    scan2_kernel<<<1, 256>>>();
    scan3_kernel<<<SCAN_BLOCKS, 1024>>>();
    fill_kernel<<<eg, 256>>>(src, dst);

    agg_all_kernel<<<(N_NODES * 32) / 256, 256>>>(out);
}

// round 13
// speedup vs baseline: 1.5558x; 1.0172x over previous
#include <cuda_runtime.h>
#include <cuda_fp16.h>
#include <cstdint>

#define N_NODES 65536
#define IN_FEAT 512
#define OUT_FEAT 256
#define N_REL 3
#define N_EDGES 500000
#define NEG_SLOPE 0.2f
#define EPS 1e-9f
#define NSEG (N_REL * N_NODES)          // 196608 segments
#define SCAN_BLOCKS (NSEG / 1024)       // 192
#define H2H_BLOCKS ((N_NODES * IN_FEAT / 8) / 256)   // 16384

// ---------------- scratch (static device globals; no allocs allowed) ---------
__device__ __half g_hh[(size_t)N_NODES * IN_FEAT];             // 64 MB fp16 h
__device__ __half g_Wth[(size_t)N_REL * OUT_FEAT * IN_FEAT];   // fp16 W^T [rel][n][k]
__device__ __half g_zh[(size_t)N_REL * N_NODES * OUT_FEAT];    // 96 MB z (fp16)
__device__ float  g_el3[NSEG];
__device__ float  g_er3[NSEG];
__device__ int    g_deg[NSEG];
__device__ int    g_off[NSEG + 1];
__device__ int    g_cur[NSEG];
__device__ int    g_blk[SCAN_BLOCKS];
__device__ int    g_flag[SCAN_BLOCKS];
__device__ int    g_srcs[(size_t)N_REL * N_EDGES];             // dst-sorted src ids

__device__ __forceinline__ uint32_t smem_u32(const void* p) {
    return (uint32_t)__cvta_generic_to_shared(p);
}
__device__ __forceinline__ void cp_async16(uint32_t saddr, const void* gaddr) {
    asm volatile("cp.async.cg.shared.global [%0], [%1], 16;" :: "r"(saddr), "l"(gaddr));
}

// ---------------- init: out bias + zero accumulators/counters --------------
__global__ void init_out_kernel(const float* __restrict__ b, float* __restrict__ out) {
    int i = blockIdx.x * blockDim.x + threadIdx.x;
    if (i < NSEG) {
        g_el3[i] = 0.f;
        g_er3[i] = 0.f;
        g_deg[i] = 0;
    }
    if (i < SCAN_BLOCKS) g_flag[i] = 0;
    if (i >= N_NODES * OUT_FEAT) return;
    int f = i & (OUT_FEAT - 1);
    out[i] = b[f] + b[OUT_FEAT + f] + b[2 * OUT_FEAT + f];
}

// ---------------- prep: h->fp16 AND W->fp16 transposed, one launch ---------
__global__ void prep_kernel(const float* __restrict__ h, const float* __restrict__ W) {
    if (blockIdx.x < H2H_BLOCKS) {
        size_t i = (size_t)blockIdx.x * 256 + threadIdx.x;
        float4 v0 = ((const float4*)h)[2 * i];
        float4 v1 = ((const float4*)h)[2 * i + 1];
        __half2 o[4];
        o[0] = __floats2half2_rn(v0.x, v0.y);
        o[1] = __floats2half2_rn(v0.z, v0.w);
        o[2] = __floats2half2_rn(v1.x, v1.y);
        o[3] = __floats2half2_rn(v1.z, v1.w);
        ((uint4*)g_hh)[i] = *(uint4*)o;
    } else {
        __shared__ float t[32][33];
        int q = blockIdx.x - H2H_BLOCKS;             // 0..383
        int rel = q / 128;
        int rem = q % 128;
        int n0 = (rem & 7) * 32;                     // 8 N-tiles
        int k0 = (rem >> 3) * 32;                    // 16 K-tiles
        const float* Wr = W + (size_t)rel * IN_FEAT * OUT_FEAT;
        __half* Wt = g_Wth + (size_t)rel * IN_FEAT * OUT_FEAT;
        int tx = threadIdx.x & 31, ty = threadIdx.x >> 5;   // 32 x 8
        #pragma unroll
        for (int i = 0; i < 4; i++)
            t[ty + 8 * i][tx] = Wr[(size_t)(k0 + ty + 8 * i) * OUT_FEAT + n0 + tx];
        __syncthreads();
        #pragma unroll
        for (int i = 0; i < 4; i++)
            Wt[(size_t)(n0 + ty + 8 * i) * IN_FEAT + k0 + tx] =
                __float2half_rn(t[tx][ty + 8 * i]);
    }
}

// ---------------- FP16 tensor-core GEMM + fused logit epilogue -------------
// CTA 128x128x64(halves), 8 warps (2x4), warp m64n32, mma.m16n8k16.f16, occ 2.
// Single-sync 3-slot / depth-2 cp.async pipeline.
#define GBM 128
#define GBN 128
#define GBK 64
#define RS 72                       // smem row stride in halves (144 B)
#define A_STAGE_H (GBM * RS)
#define B_STAGE_H (GBN * RS)
#define STAGE_H (A_STAGE_H + B_STAGE_H)
#define NSTAGES 3
#define GEMM_SMEM_BYTES (NSTAGES * STAGE_H * 2)   // 110592 B
#define KITERS (IN_FEAT / GBK)      // 8

__global__ __launch_bounds__(256, 2) void gemm_f16_kernel(const float* __restrict__ al,
                                                          const float* __restrict__ ar) {
    extern __shared__ __half smem[];
    const int tid  = threadIdx.x;
    const int bx   = blockIdx.x;            // N tile (0..1)
    const int by   = blockIdx.y;            // M tile (0..511)
    const int rel  = blockIdx.z;
    const int warp = tid >> 5, lane = tid & 31;
    const int wm = warp >> 2;
    const int wn = warp & 3;

    const int a_row = wm * 64 + (lane & 7) + ((lane >> 3) & 1) * 8;
    const int a_col = ((lane >> 4) & 1) * 8;
    const int b_row = wn * 32 + (lane & 7) + ((lane >> 4) & 1) * 8;
    const int b_col = ((lane >> 3) & 1) * 8;

    const __half* Ag0 = g_hh + (size_t)(by * GBM) * IN_FEAT;
    const __half* Bg0 = g_Wth + (size_t)rel * IN_FEAT * OUT_FEAT
                              + (size_t)(bx * GBN) * IN_FEAT;
    const float* alr = al + rel * OUT_FEAT;
    const float* arr = ar + rel * OUT_FEAT;

    float acc[4][4][4];
    #pragma unroll
    for (int i = 0; i < 4; i++)
        #pragma unroll
        for (int j = 0; j < 4; j++)
            #pragma unroll
            for (int v = 0; v < 4; v++) acc[i][j][v] = 0.f;

    auto load_stage = [&](int kt, int s) {
        __half* As = smem + s * STAGE_H;
        __half* Bs = As + A_STAGE_H;
        const __half* Ag = Ag0 + kt * GBK;
        const __half* Bg = Bg0 + kt * GBK;
        #pragma unroll
        for (int i = 0; i < 4; i++) {
            int q = tid + i * 256;
            int r = q >> 3, c = q & 7;
            cp_async16(smem_u32(As + r * RS + c * 8), Ag + (size_t)r * IN_FEAT + c * 8);
        }
        #pragma unroll
        for (int i = 0; i < 4; i++) {
            int q = tid + i * 256;
            int r = q >> 3, c = q & 7;
            cp_async16(smem_u32(Bs + r * RS + c * 8), Bg + (size_t)r * IN_FEAT + c * 8);
        }
    };

    load_stage(0, 0);
    asm volatile("cp.async.commit_group;");
    load_stage(1, 1);
    asm volatile("cp.async.commit_group;");

    for (int kt = 0; kt < KITERS; kt++) {
        // stage kt ready when <=1 newer group pending
        asm volatile("cp.async.wait_group 1;");
        __syncthreads();   // ONLY barrier: also frees slot consumed last iter

        // prefetch kt+2 into slot (kt+2)%3 == (kt-1)%3 (freed by the barrier)
        if (kt + 2 < KITERS) load_stage(kt + 2, (kt + 2) % NSTAGES);
        asm volatile("cp.async.commit_group;");

        const __half* As = smem + (kt % NSTAGES) * STAGE_H;
        const __half* Bs = As + A_STAGE_H;

        #pragma unroll
        for (int k16 = 0; k16 < GBK / 16; k16++) {
            uint32_t a[4][4];
            #pragma unroll
            for (int i = 0; i < 4; i++) {
                uint32_t addr = smem_u32(As + (a_row + i * 16) * RS + k16 * 16 + a_col);
                asm volatile("ldmatrix.sync.aligned.m8n8.x4.shared.b16 {%0,%1,%2,%3}, [%4];"
                             : "=r"(a[i][0]), "=r"(a[i][1]), "=r"(a[i][2]), "=r"(a[i][3])
                             : "r"(addr));
            }
            uint32_t bf[4][2];
            #pragma unroll
            for (int jj = 0; jj < 2; jj++) {
                uint32_t addr = smem_u32(Bs + (b_row + jj * 16) * RS + k16 * 16 + b_col);
                asm volatile("ldmatrix.sync.aligned.m8n8.x4.shared.b16 {%0,%1,%2,%3}, [%4];"
                             : "=r"(bf[2*jj][0]), "=r"(bf[2*jj][1]),
                               "=r"(bf[2*jj+1][0]), "=r"(bf[2*jj+1][1])
                             : "r"(addr));
            }
            #pragma unroll
            for (int i = 0; i < 4; i++)
                #pragma unroll
                for (int j = 0; j < 4; j++) {
                    asm volatile(
                        "mma.sync.aligned.m16n8k16.row.col.f32.f16.f16.f32 "
                        "{%0,%1,%2,%3}, {%4,%5,%6,%7}, {%8,%9}, {%0,%1,%2,%3};"
                        : "+f"(acc[i][j][0]), "+f"(acc[i][j][1]),
                          "+f"(acc[i][j][2]), "+f"(acc[i][j][3])
                        : "r"(a[i][0]), "r"(a[i][1]), "r"(a[i][2]), "r"(a[i][3]),
                          "r"(bf[j][0]), "r"(bf[j][1]));
                }
        }
    }

    // ------- epilogue: write z fp16, fused el/er dots (fp32) ---------------
    __half* zb = g_zh + (size_t)rel * N_NODES * OUT_FEAT;
    float* elb = g_el3 + rel * N_NODES;
    float* erb = g_er3 + rel * N_NODES;
    const int row0 = by * GBM + wm * 64;
    const int col0 = bx * GBN + wn * 32;
    const int gr = lane >> 2;
    const int gc = (lane & 3) * 2;
    #pragma unroll
    for (int i = 0; i < 4; i++) {
        __half* r0p = zb + (size_t)(row0 + i * 16 + gr) * OUT_FEAT + col0 + gc;
        __half* r1p = r0p + (size_t)8 * OUT_FEAT;
        float el0 = 0.f, er0 = 0.f, el1 = 0.f, er1 = 0.f;
        #pragma unroll
        for (int j = 0; j < 4; j++) {
            int c = col0 + j * 8 + gc;
            float a0 = __ldg(alr + c), a1 = __ldg(alr + c + 1);
            float q0 = __ldg(arr + c), q1 = __ldg(arr + c + 1);
            *(__half2*)(r0p + j * 8) = __floats2half2_rn(acc[i][j][0], acc[i][j][1]);
            *(__half2*)(r1p + j * 8) = __floats2half2_rn(acc[i][j][2], acc[i][j][3]);
            el0 = fmaf(acc[i][j][0], a0, fmaf(acc[i][j][1], a1, el0));
            er0 = fmaf(acc[i][j][0], q0, fmaf(acc[i][j][1], q1, er0));
            el1 = fmaf(acc[i][j][2], a0, fmaf(acc[i][j][3], a1, el1));
            er1 = fmaf(acc[i][j][2], q0, fmaf(acc[i][j][3], q1, er1));
        }
        #pragma unroll
        for (int o = 1; o <= 2; o <<= 1) {
            el0 += __shfl_xor_sync(0xFFFFFFFFu, el0, o);
            er0 += __shfl_xor_sync(0xFFFFFFFFu, er0, o);
            el1 += __shfl_xor_sync(0xFFFFFFFFu, el1, o);
            er1 += __shfl_xor_sync(0xFFFFFFFFu, er1, o);
        }
        if ((lane & 3) == 0) {
            int r0 = row0 + i * 16 + gr;
            atomicAdd(&elb[r0], el0);
            atomicAdd(&erb[r0], er0);
            atomicAdd(&elb[r0 + 8], el1);
            atomicAdd(&erb[r0 + 8], er1);
        }
    }
}

// ---------------- CSR: histogram ------------------------------------------
__global__ void hist_kernel(const int* __restrict__ dst) {
    int i = blockIdx.x * blockDim.x + threadIdx.x;
    if (i >= N_REL * N_EDGES) return;
    int r = i / N_EDGES;
    atomicAdd(&g_deg[r * N_NODES + dst[i]], 1);
}

// ---------------- CSR: full scan in ONE kernel (192 co-resident blocks) ----
__global__ void scan_all_kernel() {
    __shared__ int s[1024];
    __shared__ int s_off;
    int t = threadIdx.x, b = blockIdx.x;
    int g = b * 1024 + t;
    int own = g_deg[g];
    s[t] = own;
    __syncthreads();
    #pragma unroll
    for (int o = 1; o < 1024; o <<= 1) {
        int v = (t >= o) ? s[t - o] : 0;
        __syncthreads();
        s[t] += v;
        __syncthreads();
    }
    int local_excl = s[t] - own;

    if (t == 0) s_off = 0;
    if (t == 1023) {                                  // publish block total
        g_blk[b] = s[1023];
        __threadfence();
        atomicExch(&g_flag[b], 1);
    }
    __syncthreads();
    if (t < b) {                                      // gather lower partials
        while (atomicAdd(&g_flag[t], 0) == 0) { }
        int p = ((volatile int*)g_blk)[t];
        atomicAdd(&s_off, p);
    }
    __syncthreads();
    int v = local_excl + s_off;
    g_off[g] = v;
    g_cur[g] = v;
    if (g == 0) g_off[NSEG] = N_REL * N_EDGES;
}

__global__ void fill_kernel(const int* __restrict__ src, const int* __restrict__ dst) {
    int i = blockIdx.x * blockDim.x + threadIdx.x;
    if (i >= N_REL * N_EDGES) return;
    int r = i / N_EDGES;
    int pos = atomicAdd(&g_cur[r * N_NODES + dst[i]], 1);
    g_srcs[pos] = src[i];
}

// ---------------- aggregation: warp per dst node, ALL relations ------------
__global__ __launch_bounds__(256) void agg_all_kernel(float* __restrict__ out) {
    int node = (blockIdx.x * blockDim.x + threadIdx.x) >> 5;
    int lane = threadIdx.x & 31;
    if (node >= N_NODES) return;

    float tot[8] = {0.f, 0.f, 0.f, 0.f, 0.f, 0.f, 0.f, 0.f};
    bool any = false;

    #pragma unroll
    for (int rel = 0; rel < N_REL; rel++) {
        const int base = rel * N_NODES;
        const int beg = g_off[base + node];
        const int end = g_off[base + node + 1];
        if (beg == end) continue;
        any = true;

        const float erd = g_er3[base + node];
        const __half* zb = g_zh + (size_t)rel * N_NODES * OUT_FEAT;
        const float* elb = g_el3 + base;

        float acc[8] = {0.f, 0.f, 0.f, 0.f, 0.f, 0.f, 0.f, 0.f};
        float denom = 0.f;

        for (int c = beg; c < end; c += 32) {
            int idx = c + lane;
            int s = 0;
            float w = 0.f;
            if (idx < end) {
                s = g_srcs[idx];
                float e = elb[s] + erd;
                e = e >= 0.f ? e : NEG_SLOPE * e;
                w = expf(e);
            }
            float ws = w;
            #pragma unroll
            for (int o = 16; o; o >>= 1) ws += __shfl_xor_sync(0xFFFFFFFFu, ws, o);
            denom += ws;

            int cnt = min(32, end - c);
            for (int j = 0; j < cnt; j++) {
                int   sj = __shfl_sync(0xFFFFFFFFu, s, j);
                float wj = __shfl_sync(0xFFFFFFFFu, w, j);
                const uint4* zp = (const uint4*)(zb + (size_t)sj * OUT_FEAT);
                uint4 p = zp[lane];
                float2 f0 = __half22float2(*(__half2*)&p.x);
                float2 f1 = __half22float2(*(__half2*)&p.y);
                float2 f2 = __half22float2(*(__half2*)&p.z);
                float2 f3 = __half22float2(*(__half2*)&p.w);
                acc[0] = fmaf(wj, f0.x, acc[0]); acc[1] = fmaf(wj, f0.y, acc[1]);
                acc[2] = fmaf(wj, f1.x, acc[2]); acc[3] = fmaf(wj, f1.y, acc[3]);
                acc[4] = fmaf(wj, f2.x, acc[4]); acc[5] = fmaf(wj, f2.y, acc[5]);
                acc[6] = fmaf(wj, f3.x, acc[6]); acc[7] = fmaf(wj, f3.y, acc[7]);
            }
        }

        const float inv = 1.f / (denom + EPS);
        #pragma unroll
        for (int k = 0; k < 8; k++) tot[k] = fmaf(acc[k], inv, tot[k]);
    }

    if (!any) return;
    float4* op = (float4*)(out + (size_t)node * OUT_FEAT) + lane * 2;
    float4 o0 = op[0], o1 = op[1];
    o0.x += tot[0]; o0.y += tot[1]; o0.z += tot[2]; o0.w += tot[3];
    o1.x += tot[4]; o1.y += tot[5]; o1.z += tot[6]; o1.w += tot[7];
    op[0] = o0; op[1] = o1;
}

// ---------------- launch ----------------------------------------------------
extern "C" void kernel_launch(void* const* d_in, const int* in_sizes, int n_in,
                              void* d_out, int out_size) {
    const float* h   = (const float*)d_in[0];
    const float* W   = (const float*)d_in[1];
    const float* al  = (const float*)d_in[2];
    const float* ar  = (const float*)d_in[3];
    const float* b   = (const float*)d_in[4];
    const int*   src = (const int*)d_in[5];
    const int*   dst = (const int*)d_in[6];
    float*       out = (float*)d_out;

    cudaFuncSetAttribute(gemm_f16_kernel,
                         cudaFuncAttributeMaxDynamicSharedMemorySize, GEMM_SMEM_BYTES);

    // launches 1..3; GEMM stays launch #4 (ncu capture slot)
    init_out_kernel<<<(N_NODES * OUT_FEAT + 255) / 256, 256>>>(b, out);
    prep_kernel<<<H2H_BLOCKS + 384, 256>>>(h, W);
    int eg = (N_REL * N_EDGES + 255) / 256;
    hist_kernel<<<eg, 256>>>(dst);

    dim3 gemm_grid(OUT_FEAT / GBN, N_NODES / GBM, N_REL);   // (2, 512, 3)
    gemm_f16_kernel<<<gemm_grid, 256, GEMM_SMEM_BYTES>>>(al, ar);

    scan_all_kernel<<<SCAN_BLOCKS, 1024>>>();
    fill_kernel<<<eg, 256>>>(src, dst);

    agg_all_kernel<<<(N_NODES * 32) / 256, 256>>>(out);
}

// round 14
// speedup vs baseline: 1.5625x; 1.0043x over previous
#include <cuda_runtime.h>
#include <cuda_fp16.h>
#include <cstdint>

#define N_NODES 65536
#define IN_FEAT 512
#define OUT_FEAT 256
#define N_REL 3
#define N_EDGES 500000
#define NEG_SLOPE 0.2f
#define EPS 1e-9f
#define NSEG (N_REL * N_NODES)          // 196608 segments
#define SCAN_BLOCKS (NSEG / 1024)       // 192
#define H2H_BLOCKS ((N_NODES * IN_FEAT / 8) / 256)   // 16384
#define WT_BLOCKS (N_REL * 128)                      // 384
#define HIST_BLOCKS ((N_REL * N_EDGES + 255) / 256)  // 5860
#define FILL_BLOCKS ((N_REL * N_EDGES + 1023) / 1024) // 1465

// ---------------- scratch (static device globals; no allocs allowed) ---------
__device__ __half g_hh[(size_t)N_NODES * IN_FEAT];             // 64 MB fp16 h
__device__ __half g_Wth[(size_t)N_REL * OUT_FEAT * IN_FEAT];   // fp16 W^T [rel][n][k]
__device__ __half g_zh[(size_t)N_REL * N_NODES * OUT_FEAT];    // 96 MB z (fp16)
__device__ float  g_el3[NSEG];
__device__ float  g_er3[NSEG];
__device__ int    g_deg[NSEG];
__device__ int    g_off[NSEG + 1];
__device__ int    g_cur[NSEG];
__device__ int    g_blk[SCAN_BLOCKS];
__device__ int    g_flag[SCAN_BLOCKS];
__device__ int    g_scan_done;
__device__ int    g_srcs[(size_t)N_REL * N_EDGES];             // dst-sorted src ids

__device__ __forceinline__ uint32_t smem_u32(const void* p) {
    return (uint32_t)__cvta_generic_to_shared(p);
}
__device__ __forceinline__ void cp_async16(uint32_t saddr, const void* gaddr) {
    asm volatile("cp.async.cg.shared.global [%0], [%1], 16;" :: "r"(saddr), "l"(gaddr));
}

// ---------------- init: out bias + zero accumulators/counters --------------
__global__ void init_out_kernel(const float* __restrict__ b, float* __restrict__ out) {
    int i = blockIdx.x * blockDim.x + threadIdx.x;
    if (i < NSEG) {
        g_el3[i] = 0.f;
        g_er3[i] = 0.f;
        g_deg[i] = 0;
    }
    if (i < SCAN_BLOCKS) g_flag[i] = 0;
    if (i == 0) g_scan_done = 0;
    if (i >= N_NODES * OUT_FEAT) return;
    int f = i & (OUT_FEAT - 1);
    out[i] = b[f] + b[OUT_FEAT + f] + b[2 * OUT_FEAT + f];
}

// ---------------- prep+hist: h->fp16, W->fp16^T, dst histogram -------------
__global__ void prep_hist_kernel(const float* __restrict__ h, const float* __restrict__ W,
                                 const int* __restrict__ dst) {
    if (blockIdx.x < H2H_BLOCKS) {
        size_t i = (size_t)blockIdx.x * 256 + threadIdx.x;
        float4 v0 = ((const float4*)h)[2 * i];
        float4 v1 = ((const float4*)h)[2 * i + 1];
        __half2 o[4];
        o[0] = __floats2half2_rn(v0.x, v0.y);
        o[1] = __floats2half2_rn(v0.z, v0.w);
        o[2] = __floats2half2_rn(v1.x, v1.y);
        o[3] = __floats2half2_rn(v1.z, v1.w);
        ((uint4*)g_hh)[i] = *(uint4*)o;
    } else if (blockIdx.x < H2H_BLOCKS + WT_BLOCKS) {
        __shared__ float t[32][33];
        int q = blockIdx.x - H2H_BLOCKS;             // 0..383
        int rel = q / 128;
        int rem = q % 128;
        int n0 = (rem & 7) * 32;                     // 8 N-tiles
        int k0 = (rem >> 3) * 32;                    // 16 K-tiles
        const float* Wr = W + (size_t)rel * IN_FEAT * OUT_FEAT;
        __half* Wt = g_Wth + (size_t)rel * IN_FEAT * OUT_FEAT;
        int tx = threadIdx.x & 31, ty = threadIdx.x >> 5;   // 32 x 8
        #pragma unroll
        for (int i = 0; i < 4; i++)
            t[ty + 8 * i][tx] = Wr[(size_t)(k0 + ty + 8 * i) * OUT_FEAT + n0 + tx];
        __syncthreads();
        #pragma unroll
        for (int i = 0; i < 4; i++)
            Wt[(size_t)(n0 + ty + 8 * i) * IN_FEAT + k0 + tx] =
                __float2half_rn(t[tx][ty + 8 * i]);
    } else {
        int i = (blockIdx.x - H2H_BLOCKS - WT_BLOCKS) * 256 + threadIdx.x;
        if (i >= N_REL * N_EDGES) return;
        int r = i / N_EDGES;
        atomicAdd(&g_deg[r * N_NODES + dst[i]], 1);
    }
}

// ---------------- scan + fill in ONE kernel --------------------------------
// Blocks 0..191: cross-block exclusive scan (flag handshake), then publish
// g_scan_done. Blocks >=192: fill, gated on g_scan_done==SCAN_BLOCKS.
// Deadlock-free: 1024-thr blocks -> 296 co-resident >= 192 scan blocks,
// dispatched in ascending blockIdx.
__global__ __launch_bounds__(1024) void scan_fill_kernel(const int* __restrict__ src,
                                                         const int* __restrict__ dst) {
    int t = threadIdx.x, b = blockIdx.x;
    if (b < SCAN_BLOCKS) {
        __shared__ int s[1024];
        __shared__ int s_off;
        int g = b * 1024 + t;
        int own = g_deg[g];
        s[t] = own;
        __syncthreads();
        #pragma unroll
        for (int o = 1; o < 1024; o <<= 1) {
            int v = (t >= o) ? s[t - o] : 0;
            __syncthreads();
            s[t] += v;
            __syncthreads();
        }
        int local_excl = s[t] - own;

        if (t == 0) s_off = 0;
        if (t == 1023) {                              // publish block total
            g_blk[b] = s[1023];
            __threadfence();
            atomicExch(&g_flag[b], 1);
        }
        __syncthreads();
        if (t < b) {                                  // gather lower partials
            while (atomicAdd(&g_flag[t], 0) == 0) { }
            int p = ((volatile int*)g_blk)[t];
            atomicAdd(&s_off, p);
        }
        __syncthreads();
        int v = local_excl + s_off;
        g_off[g] = v;
        g_cur[g] = v;
        if (g == 0) g_off[NSEG] = N_REL * N_EDGES;
        __syncthreads();
        if (t == 0) {
            __threadfence();
            atomicAdd(&g_scan_done, 1);
        }
    } else {
        if (t == 0) {
            while (atomicAdd(&g_scan_done, 0) < SCAN_BLOCKS) { }
        }
        __syncthreads();
        int i = (b - SCAN_BLOCKS) * 1024 + t;
        if (i >= N_REL * N_EDGES) return;
        int r = i / N_EDGES;
        int pos = atomicAdd(&g_cur[r * N_NODES + dst[i]], 1);
        g_srcs[pos] = src[i];
    }
}

// ---------------- FP16 tensor-core GEMM + fused logit epilogue -------------
// CTA 128x128x64(halves), 8 warps (2x4), warp m64n32, mma.m16n8k16.f16, occ 2.
#define GBM 128
#define GBN 128
#define GBK 64
#define RS 72                       // smem row stride in halves (144 B)
#define A_STAGE_H (GBM * RS)
#define B_STAGE_H (GBN * RS)
#define STAGE_H (A_STAGE_H + B_STAGE_H)
#define NSTAGES 3
#define GEMM_SMEM_BYTES (NSTAGES * STAGE_H * 2)   // 110592 B
#define KITERS (IN_FEAT / GBK)      // 8

__global__ __launch_bounds__(256, 2) void gemm_f16_kernel(const float* __restrict__ al,
                                                          const float* __restrict__ ar) {
    extern __shared__ __half smem[];
    const int tid  = threadIdx.x;
    const int bx   = blockIdx.x;            // N tile (0..1)
    const int by   = blockIdx.y;            // M tile (0..511)
    const int rel  = blockIdx.z;
    const int warp = tid >> 5, lane = tid & 31;
    const int wm = warp >> 2;
    const int wn = warp & 3;

    const int a_row = wm * 64 + (lane & 7) + ((lane >> 3) & 1) * 8;
    const int a_col = ((lane >> 4) & 1) * 8;
    const int b_row = wn * 32 + (lane & 7) + ((lane >> 4) & 1) * 8;
    const int b_col = ((lane >> 3) & 1) * 8;

    const __half* Ag0 = g_hh + (size_t)(by * GBM) * IN_FEAT;
    const __half* Bg0 = g_Wth + (size_t)rel * IN_FEAT * OUT_FEAT
                              + (size_t)(bx * GBN) * IN_FEAT;
    const float* alr = al + rel * OUT_FEAT;
    const float* arr = ar + rel * OUT_FEAT;

    float acc[4][4][4];
    #pragma unroll
    for (int i = 0; i < 4; i++)
        #pragma unroll
        for (int j = 0; j < 4; j++)
            #pragma unroll
            for (int v = 0; v < 4; v++) acc[i][j][v] = 0.f;

    auto load_stage = [&](int kt, int s) {
        __half* As = smem + s * STAGE_H;
        __half* Bs = As + A_STAGE_H;
        const __half* Ag = Ag0 + kt * GBK;
        const __half* Bg = Bg0 + kt * GBK;
        #pragma unroll
        for (int i = 0; i < 4; i++) {
            int q = tid + i * 256;
            int r = q >> 3, c = q & 7;
            cp_async16(smem_u32(As + r * RS + c * 8), Ag + (size_t)r * IN_FEAT + c * 8);
        }
        #pragma unroll
        for (int i = 0; i < 4; i++) {
            int q = tid + i * 256;
            int r = q >> 3, c = q & 7;
            cp_async16(smem_u32(Bs + r * RS + c * 8), Bg + (size_t)r * IN_FEAT + c * 8);
        }
    };

    load_stage(0, 0);
    asm volatile("cp.async.commit_group;");
    load_stage(1, 1);
    asm volatile("cp.async.commit_group;");

    for (int kt = 0; kt < KITERS; kt++) {
        asm volatile("cp.async.wait_group 1;");
        __syncthreads();

        if (kt + 2 < KITERS) load_stage(kt + 2, (kt + 2) % NSTAGES);
        asm volatile("cp.async.commit_group;");

        const __half* As = smem + (kt % NSTAGES) * STAGE_H;
        const __half* Bs = As + A_STAGE_H;

        #pragma unroll
        for (int k16 = 0; k16 < GBK / 16; k16++) {
            uint32_t a[4][4];
            #pragma unroll
            for (int i = 0; i < 4; i++) {
                uint32_t addr = smem_u32(As + (a_row + i * 16) * RS + k16 * 16 + a_col);
                asm volatile("ldmatrix.sync.aligned.m8n8.x4.shared.b16 {%0,%1,%2,%3}, [%4];"
                             : "=r"(a[i][0]), "=r"(a[i][1]), "=r"(a[i][2]), "=r"(a[i][3])
                             : "r"(addr));
            }
            uint32_t bf[4][2];
            #pragma unroll
            for (int jj = 0; jj < 2; jj++) {
                uint32_t addr = smem_u32(Bs + (b_row + jj * 16) * RS + k16 * 16 + b_col);
                asm volatile("ldmatrix.sync.aligned.m8n8.x4.shared.b16 {%0,%1,%2,%3}, [%4];"
                             : "=r"(bf[2*jj][0]), "=r"(bf[2*jj][1]),
                               "=r"(bf[2*jj+1][0]), "=r"(bf[2*jj+1][1])
                             : "r"(addr));
            }
            #pragma unroll
            for (int i = 0; i < 4; i++)
                #pragma unroll
                for (int j = 0; j < 4; j++) {
                    asm volatile(
                        "mma.sync.aligned.m16n8k16.row.col.f32.f16.f16.f32 "
                        "{%0,%1,%2,%3}, {%4,%5,%6,%7}, {%8,%9}, {%0,%1,%2,%3};"
                        : "+f"(acc[i][j][0]), "+f"(acc[i][j][1]),
                          "+f"(acc[i][j][2]), "+f"(acc[i][j][3])
                        : "r"(a[i][0]), "r"(a[i][1]), "r"(a[i][2]), "r"(a[i][3]),
                          "r"(bf[j][0]), "r"(bf[j][1]));
                }
        }
    }

    // ------- epilogue: write z fp16, fused el/er dots (fp32) ---------------
    __half* zb = g_zh + (size_t)rel * N_NODES * OUT_FEAT;
    float* elb = g_el3 + rel * N_NODES;
    float* erb = g_er3 + rel * N_NODES;
    const int row0 = by * GBM + wm * 64;
    const int col0 = bx * GBN + wn * 32;
    const int gr = lane >> 2;
    const int gc = (lane & 3) * 2;
    #pragma unroll
    for (int i = 0; i < 4; i++) {
        __half* r0p = zb + (size_t)(row0 + i * 16 + gr) * OUT_FEAT + col0 + gc;
        __half* r1p = r0p + (size_t)8 * OUT_FEAT;
        float el0 = 0.f, er0 = 0.f, el1 = 0.f, er1 = 0.f;
        #pragma unroll
        for (int j = 0; j < 4; j++) {
            int c = col0 + j * 8 + gc;
            float a0 = __ldg(alr + c), a1 = __ldg(alr + c + 1);
            float q0 = __ldg(arr + c), q1 = __ldg(arr + c + 1);
            *(__half2*)(r0p + j * 8) = __floats2half2_rn(acc[i][j][0], acc[i][j][1]);
            *(__half2*)(r1p + j * 8) = __floats2half2_rn(acc[i][j][2], acc[i][j][3]);
            el0 = fmaf(acc[i][j][0], a0, fmaf(acc[i][j][1], a1, el0));
            er0 = fmaf(acc[i][j][0], q0, fmaf(acc[i][j][1], q1, er0));
            el1 = fmaf(acc[i][j][2], a0, fmaf(acc[i][j][3], a1, el1));
            er1 = fmaf(acc[i][j][2], q0, fmaf(acc[i][j][3], q1, er1));
        }
        #pragma unroll
        for (int o = 1; o <= 2; o <<= 1) {
            el0 += __shfl_xor_sync(0xFFFFFFFFu, el0, o);
            er0 += __shfl_xor_sync(0xFFFFFFFFu, er0, o);
            el1 += __shfl_xor_sync(0xFFFFFFFFu, el1, o);
            er1 += __shfl_xor_sync(0xFFFFFFFFu, er1, o);
        }
        if ((lane & 3) == 0) {
            int r0 = row0 + i * 16 + gr;
            atomicAdd(&elb[r0], el0);
            atomicAdd(&erb[r0], er0);
            atomicAdd(&elb[r0 + 8], el1);
            atomicAdd(&erb[r0 + 8], er1);
        }
    }
}

// ---------------- aggregation: warp per dst node, ALL relations ------------
__global__ __launch_bounds__(256) void agg_all_kernel(float* __restrict__ out) {
    int node = (blockIdx.x * blockDim.x + threadIdx.x) >> 5;
    int lane = threadIdx.x & 31;
    if (node >= N_NODES) return;

    float tot[8] = {0.f, 0.f, 0.f, 0.f, 0.f, 0.f, 0.f, 0.f};
    bool any = false;

    #pragma unroll
    for (int rel = 0; rel < N_REL; rel++) {
        const int base = rel * N_NODES;
        const int beg = g_off[base + node];
        const int end = g_off[base + node + 1];
        if (beg == end) continue;
        any = true;

        const float erd = g_er3[base + node];
        const __half* zb = g_zh + (size_t)rel * N_NODES * OUT_FEAT;
        const float* elb = g_el3 + base;

        float acc[8] = {0.f, 0.f, 0.f, 0.f, 0.f, 0.f, 0.f, 0.f};
        float denom = 0.f;

        for (int c = beg; c < end; c += 32) {
            int idx = c + lane;
            int s = 0;
            float w = 0.f;
            if (idx < end) {
                s = g_srcs[idx];
                float e = elb[s] + erd;
                e = e >= 0.f ? e : NEG_SLOPE * e;
                w = __expf(e);
            }
            float ws = w;
            #pragma unroll
            for (int o = 16; o; o >>= 1) ws += __shfl_xor_sync(0xFFFFFFFFu, ws, o);
            denom += ws;

            int cnt = min(32, end - c);
            for (int j = 0; j < cnt; j++) {
                int   sj = __shfl_sync(0xFFFFFFFFu, s, j);
                float wj = __shfl_sync(0xFFFFFFFFu, w, j);
                const uint4* zp = (const uint4*)(zb + (size_t)sj * OUT_FEAT);
                uint4 p = zp[lane];
                float2 f0 = __half22float2(*(__half2*)&p.x);
                float2 f1 = __half22float2(*(__half2*)&p.y);
                float2 f2 = __half22float2(*(__half2*)&p.z);
                float2 f3 = __half22float2(*(__half2*)&p.w);
                acc[0] = fmaf(wj, f0.x, acc[0]); acc[1] = fmaf(wj, f0.y, acc[1]);
                acc[2] = fmaf(wj, f1.x, acc[2]); acc[3] = fmaf(wj, f1.y, acc[3]);
                acc[4] = fmaf(wj, f2.x, acc[4]); acc[5] = fmaf(wj, f2.y, acc[5]);
                acc[6] = fmaf(wj, f3.x, acc[6]); acc[7] = fmaf(wj, f3.y, acc[7]);
            }
        }

        const float inv = 1.f / (denom + EPS);
        #pragma unroll
        for (int k = 0; k < 8; k++) tot[k] = fmaf(acc[k], inv, tot[k]);
    }

    if (!any) return;
    float4* op = (float4*)(out + (size_t)node * OUT_FEAT) + lane * 2;
    float4 o0 = op[0], o1 = op[1];
    o0.x += tot[0]; o0.y += tot[1]; o0.z += tot[2]; o0.w += tot[3];
    o1.x += tot[4]; o1.y += tot[5]; o1.z += tot[6]; o1.w += tot[7];
    op[0] = o0; op[1] = o1;
}

// ---------------- launch ----------------------------------------------------
extern "C" void kernel_launch(void* const* d_in, const int* in_sizes, int n_in,
                              void* d_out, int out_size) {
    const float* h   = (const float*)d_in[0];
    const float* W   = (const float*)d_in[1];
    const float* al  = (const float*)d_in[2];
    const float* ar  = (const float*)d_in[3];
    const float* b   = (const float*)d_in[4];
    const int*   src = (const int*)d_in[5];
    const int*   dst = (const int*)d_in[6];
    float*       out = (float*)d_out;

    cudaFuncSetAttribute(gemm_f16_kernel,
                         cudaFuncAttributeMaxDynamicSharedMemorySize, GEMM_SMEM_BYTES);

    // 1: init, 2: prep+hist, 3: scan+fill, 4: GEMM (ncu slot), 5: agg
    init_out_kernel<<<(N_NODES * OUT_FEAT + 255) / 256, 256>>>(b, out);
    prep_hist_kernel<<<H2H_BLOCKS + WT_BLOCKS + HIST_BLOCKS, 256>>>(h, W, dst);
    scan_fill_kernel<<<SCAN_BLOCKS + FILL_BLOCKS, 1024>>>(src, dst);

    dim3 gemm_grid(OUT_FEAT / GBN, N_NODES / GBM, N_REL);   // (2, 512, 3)
    gemm_f16_kernel<<<gemm_grid, 256, GEMM_SMEM_BYTES>>>(al, ar);

    agg_all_kernel<<<(N_NODES * 32) / 256, 256>>>(out);
}